// round 9
// baseline (speedup 1.0000x reference)
#include <cuda_runtime.h>
#include <cuda_fp16.h>
#include <cstddef>
#include <cstdint>

#define NN    100000
#define NEDGE 3200000
#define FEAT  256
#define HID   128
#define NOUT  64
#define HOPS  3
#define CAP   ((size_t)NN * HID)

#define W_SCALE 32767.0f
#define W_INV   (1.0f / 32767.0f)

// 8 fp16 hop buffers: s-dir h0..h3, t-dir h0..h3
__device__ __half    g_hbuf[8][CAP];
__device__ int       g_deg[2][NN];
__device__ int       g_rowptr[2][NN + 1];
__device__ int       g_fill[2][NN];
__device__ int       g_bsum[2][128];
__device__ uint32_t  g_csr[2][NEDGE];   // packed: (nbr << 15) | q15(weight)

// ======================= CSR build =======================
__global__ __launch_bounds__(256)
void hist_kernel(const int* __restrict__ erow, const int* __restrict__ ecol,
                 int* __restrict__ deg_s, int* __restrict__ deg_t, int E) {
    int e = blockIdx.x * blockDim.x + threadIdx.x;
    if (e < E) {
        atomicAdd(&deg_s[erow[e]], 1);   // no return use -> REDG
        atomicAdd(&deg_t[ecol[e]], 1);
    }
}

// per-1024-chunk exclusive scan + chunk totals; both directions via blockIdx.y
__global__ __launch_bounds__(1024)
void scan_chunk2(const int* __restrict__ deg_s, int* __restrict__ rp_s, int* __restrict__ bs_s,
                 const int* __restrict__ deg_t, int* __restrict__ rp_t, int* __restrict__ bs_t,
                 int n) {
    const int* in = blockIdx.y ? deg_t : deg_s;
    int* out = blockIdx.y ? rp_t : rp_s;
    int* bsum = blockIdx.y ? bs_t : bs_s;
    __shared__ int sh[1024];
    int t = threadIdx.x;
    int g = blockIdx.x * 1024 + t;
    int v = (g < n) ? in[g] : 0;
    sh[t] = v;
    __syncthreads();
    #pragma unroll
    for (int off = 1; off < 1024; off <<= 1) {
        int x = (t >= off) ? sh[t - off] : 0;
        __syncthreads();
        sh[t] += x;
        __syncthreads();
    }
    if (g < n) out[g] = sh[t] - v;         // exclusive within chunk
    if (t == 1023) bsum[blockIdx.x] = sh[1023];
}

// adds chunk prefix (in-block scan over <=128 chunk totals); writes fill too
__global__ __launch_bounds__(256)
void finalize2(int* __restrict__ rp_s, const int* __restrict__ bs_s, int* __restrict__ fil_s,
               int* __restrict__ rp_t, const int* __restrict__ bs_t, int* __restrict__ fil_t,
               int n, int nchunks, int total) {
    int* rowptr = blockIdx.y ? rp_t : rp_s;
    const int* bs = blockIdx.y ? bs_t : bs_s;
    int* fill = blockIdx.y ? fil_t : fil_s;
    __shared__ int sh[128];
    int t = threadIdx.x;
    if (t < 128) sh[t] = (t < nchunks) ? bs[t] : 0;
    __syncthreads();
    #pragma unroll
    for (int off = 1; off < 128; off <<= 1) {
        int x = (t >= off && t < 128) ? sh[t - off] : 0;
        __syncthreads();
        if (t < 128) sh[t] += x;
        __syncthreads();
    }
    int chunk = (blockIdx.x * 256) >> 10;       // constant per block (256 | 1024)
    int pre = chunk ? sh[chunk - 1] : 0;
    int g = blockIdx.x * 256 + t;
    if (g < n) {
        int v = rowptr[g] + pre;
        rowptr[g] = v;
        fill[g] = v;
    }
    if (g == n) rowptr[n] = total;
}

__device__ __forceinline__ void stcs_u32(uint32_t* addr, uint32_t v) {
    asm volatile("st.global.cs.u32 [%0], %1;" :: "l"(addr), "r"(v) : "memory");
}

// 2 edges per thread; all 4 atomics issued before any CSR store (overlap latency)
__global__ __launch_bounds__(256)
void scatter_kernel(const int* __restrict__ erow, const int* __restrict__ ecol,
                    const float* __restrict__ ew,
                    int* __restrict__ fill_s, int* __restrict__ fill_t,
                    uint32_t* __restrict__ csr_s, uint32_t* __restrict__ csr_t, int E) {
    int e0 = blockIdx.x * (blockDim.x * 2) + threadIdx.x;
    int e1 = e0 + blockDim.x;
    bool v0 = (e0 < E), v1 = (e1 < E);

    int r0 = 0, c0 = 0, r1 = 0, c1 = 0;
    uint32_t q0 = 0, q1 = 0;
    if (v0) {
        r0 = erow[e0]; c0 = ecol[e0];
        q0 = (uint32_t)__float2int_rn(ew[e0] * W_SCALE);
    }
    if (v1) {
        r1 = erow[e1]; c1 = ecol[e1];
        q1 = (uint32_t)__float2int_rn(ew[e1] * W_SCALE);
    }

    int ps0 = 0, pt0 = 0, ps1 = 0, pt1 = 0;
    if (v0) ps0 = atomicAdd(&fill_s[r0], 1);
    if (v1) ps1 = atomicAdd(&fill_s[r1], 1);
    if (v0) pt0 = atomicAdd(&fill_t[c0], 1);
    if (v1) pt1 = atomicAdd(&fill_t[c1], 1);

    if (v0) stcs_u32(csr_s + ps0, ((uint32_t)c0 << 15) | q0);
    if (v1) stcs_u32(csr_s + ps1, ((uint32_t)c1 << 15) | q1);
    if (v0) stcs_u32(csr_t + pt0, ((uint32_t)r0 << 15) | q0);
    if (v1) stcs_u32(csr_t + pt1, ((uint32_t)r1 << 15) | q1);
}

// ======================= SPMM (fp16 gather, fp32 accumulate) ================
// both directions in one launch; next[i] = fp16( sum_e w_e * x[nbr_e] )
// warp per node; lane owns 4 halves (8B). CSR 32-entry batched via shfl;
// remainder processed in unrolled chunks of 8 for load MLP.
__global__ __launch_bounds__(256)
void spmm2_kernel(const int* __restrict__ rp_s, const int* __restrict__ rp_t,
                  const uint32_t* __restrict__ csr_s, const uint32_t* __restrict__ csr_t,
                  __half* __restrict__ hb, int h, int n) {
    int dir = blockIdx.y;
    const int* rowptr = dir ? rp_t : rp_s;
    const uint32_t* csr = dir ? csr_t : csr_s;
    const __half* x = hb + (size_t)(dir * 4 + h - 1) * CAP;
    __half* next = hb + (size_t)(dir * 4 + h) * CAP;

    int lane = threadIdx.x & 31;
    int node = (int)((blockIdx.x * blockDim.x + threadIdx.x) >> 5);
    if (node >= n) return;
    int beg = rowptr[node];
    int end = rowptr[node + 1];
    float4 acc = make_float4(0.f, 0.f, 0.f, 0.f);
    const uint2* xb = (const uint2*)x + lane;

    int p = beg;
    for (; p + 32 <= end; p += 32) {
        uint32_t pk;
        asm volatile("ld.global.cs.u32 %0, [%1];" : "=r"(pk) : "l"(csr + p + lane));
        #pragma unroll
        for (int j = 0; j < 32; j++) {
            uint32_t pe = __shfl_sync(0xffffffffu, pk, j);
            int   c  = (int)(pe >> 15);
            float wv = (float)(pe & 0x7FFFu) * W_INV;
            uint2 raw = __ldg(xb + (size_t)c * 32);
            float2 v0 = __half22float2(*(__half2*)&raw.x);
            float2 v1 = __half22float2(*(__half2*)&raw.y);
            acc.x = fmaf(wv, v0.x, acc.x);
            acc.y = fmaf(wv, v0.y, acc.y);
            acc.z = fmaf(wv, v1.x, acc.z);
            acc.w = fmaf(wv, v1.y, acc.w);
        }
    }
    int rem = end - p;
    if (rem > 0) {
        uint32_t pk = (lane < rem) ? csr[p + lane] : 0u;
        int j = 0;
        for (; j + 8 <= rem; j += 8) {
            #pragma unroll
            for (int jj = 0; jj < 8; jj++) {
                uint32_t pe = __shfl_sync(0xffffffffu, pk, j + jj);
                int   c  = (int)(pe >> 15);
                float wv = (float)(pe & 0x7FFFu) * W_INV;
                uint2 raw = __ldg(xb + (size_t)c * 32);
                float2 v0 = __half22float2(*(__half2*)&raw.x);
                float2 v1 = __half22float2(*(__half2*)&raw.y);
                acc.x = fmaf(wv, v0.x, acc.x);
                acc.y = fmaf(wv, v0.y, acc.y);
                acc.z = fmaf(wv, v1.x, acc.z);
                acc.w = fmaf(wv, v1.y, acc.w);
            }
        }
        for (; j < rem; j++) {
            uint32_t pe = __shfl_sync(0xffffffffu, pk, j);
            int   c  = (int)(pe >> 15);
            float wv = (float)(pe & 0x7FFFu) * W_INV;
            uint2 raw = __ldg(xb + (size_t)c * 32);
            float2 v0 = __half22float2(*(__half2*)&raw.x);
            float2 v1 = __half22float2(*(__half2*)&raw.y);
            acc.x = fmaf(wv, v0.x, acc.x);
            acc.y = fmaf(wv, v0.y, acc.y);
            acc.z = fmaf(wv, v1.x, acc.z);
            acc.w = fmaf(wv, v1.y, acc.w);
        }
    }

    __half2 o2[2];
    o2[0] = __floats2half2_rn(acc.x, acc.y);
    o2[1] = __floats2half2_rn(acc.z, acc.w);
    *((uint2*)(next + (size_t)node * HID) + lane) = *(uint2*)o2;
}

// ======================= tensor-core helpers ========================
__device__ __forceinline__ uint32_t smem_u32(const void* p) {
    return (uint32_t)__cvta_generic_to_shared(p);
}
__device__ __forceinline__ void ldsm_x4(uint32_t* r, uint32_t addr) {
    asm volatile("ldmatrix.sync.aligned.m8n8.x4.shared.b16 {%0,%1,%2,%3}, [%4];"
                 : "=r"(r[0]), "=r"(r[1]), "=r"(r[2]), "=r"(r[3]) : "r"(addr));
}
__device__ __forceinline__ void ldsm_x4_t(uint32_t* r, uint32_t addr) {
    asm volatile("ldmatrix.sync.aligned.m8n8.x4.trans.shared.b16 {%0,%1,%2,%3}, [%4];"
                 : "=r"(r[0]), "=r"(r[1]), "=r"(r[2]), "=r"(r[3]) : "r"(addr));
}
__device__ __forceinline__ void mma16816(float* c, const uint32_t* a,
                                         uint32_t b0, uint32_t b1) {
    asm volatile("mma.sync.aligned.m16n8k16.row.col.f32.f16.f16.f32 "
                 "{%0,%1,%2,%3}, {%4,%5,%6,%7}, {%8,%9}, {%0,%1,%2,%3};"
                 : "+f"(c[0]), "+f"(c[1]), "+f"(c[2]), "+f"(c[3])
                 : "r"(a[0]), "r"(a[1]), "r"(a[2]), "r"(a[3]), "r"(b0), "r"(b1));
}

#define A_STRIDE 40   // halves per row (32 + 8 pad)
#define W_STRIDE 136  // halves per row (128 + 8 pad)
#define W2_STRIDE 72  // halves per row (64 + 8 pad)

// ======================= input GEMM via tensor cores ========================
// h0 = fp16(A @ W + b); both projections in one launch (blockIdx.y)
__global__ __launch_bounds__(256)
void gemm_input2_mma(const float* __restrict__ A0, const float* __restrict__ W0,
                     const float* __restrict__ bias0,
                     const float* __restrict__ A1, const float* __restrict__ W1,
                     const float* __restrict__ bias1,
                     __half* __restrict__ hb, int M) {
    const float* A    = blockIdx.y ? A1 : A0;
    const float* W    = blockIdx.y ? W1 : W0;
    const float* bias = blockIdx.y ? bias1 : bias0;
    __half* curr = hb + (size_t)(blockIdx.y * 4) * CAP;

    __shared__ __half Ah[128 * A_STRIDE];
    __shared__ __half Wh[32 * W_STRIDE];
    int tid = threadIdx.x;
    int lane = tid & 31;
    int warp = tid >> 5;
    int wm = warp >> 1;
    int wn = warp & 1;
    int row0 = blockIdx.x * 128;

    float acc[2][8][4];
    #pragma unroll
    for (int i = 0; i < 2; i++)
        #pragma unroll
        for (int j = 0; j < 8; j++)
            #pragma unroll
            for (int k = 0; k < 4; k++) acc[i][j][k] = 0.f;

    for (int k0 = 0; k0 < FEAT; k0 += 32) {
        #pragma unroll
        for (int i = 0; i < 4; i++) {
            int f = tid + i * 256;
            int r = f >> 3;
            int cg = (f & 7) * 4;
            float4 v = make_float4(0.f, 0.f, 0.f, 0.f);
            if (row0 + r < M)
                v = *(const float4*)(A + (size_t)(row0 + r) * FEAT + k0 + cg);
            __half2 h0 = __floats2half2_rn(v.x, v.y);
            __half2 h1 = __floats2half2_rn(v.z, v.w);
            *(uint2*)&Ah[r * A_STRIDE + cg] = make_uint2(*(uint32_t*)&h0, *(uint32_t*)&h1);
        }
        #pragma unroll
        for (int i = 0; i < 4; i++) {
            int f = tid + i * 256;
            int r = f >> 5;
            int cg = (f & 31) * 4;
            float4 v = *(const float4*)(W + (size_t)(k0 + r) * HID + cg);
            __half2 h0 = __floats2half2_rn(v.x, v.y);
            __half2 h1 = __floats2half2_rn(v.z, v.w);
            *(uint2*)&Wh[r * W_STRIDE + cg] = make_uint2(*(uint32_t*)&h0, *(uint32_t*)&h1);
        }
        __syncthreads();

        #pragma unroll
        for (int ks = 0; ks < 32; ks += 16) {
            uint32_t aF[2][4];
            #pragma unroll
            for (int mt = 0; mt < 2; mt++) {
                int r = wm * 32 + mt * 16 + (lane & 15);
                int c = ks + ((lane >> 4) << 3);
                ldsm_x4(aF[mt], smem_u32(&Ah[r * A_STRIDE + c]));
            }
            uint32_t bF[4][4];
            #pragma unroll
            for (int ng = 0; ng < 4; ng++) {
                int r = ks + ((lane >> 4) << 3) + (lane & 7);
                int c = wn * 64 + ng * 16 + (((lane >> 3) & 1) << 3);
                ldsm_x4_t(bF[ng], smem_u32(&Wh[r * W_STRIDE + c]));
            }
            #pragma unroll
            for (int mt = 0; mt < 2; mt++)
                #pragma unroll
                for (int nt = 0; nt < 8; nt++) {
                    int ng = nt >> 1, sel = nt & 1;
                    mma16816(acc[mt][nt], aF[mt], bF[ng][sel], bF[ng][sel + 2]);
                }
        }
        __syncthreads();
    }

    #pragma unroll
    for (int mt = 0; mt < 2; mt++) {
        int r_ = row0 + wm * 32 + mt * 16 + (lane >> 2);
        #pragma unroll
        for (int nt = 0; nt < 8; nt++) {
            int c_ = wn * 64 + nt * 8 + (lane & 3) * 2;
            float b0 = __ldg(bias + c_);
            float b1 = __ldg(bias + c_ + 1);
            if (r_ < M) {
                __half2 hv = __floats2half2_rn(acc[mt][nt][0] + b0, acc[mt][nt][1] + b1);
                *(__half2*)(curr + (size_t)r_ * HID + c_) = hv;
            }
            if (r_ + 8 < M) {
                __half2 hv = __floats2half2_rn(acc[mt][nt][2] + b0, acc[mt][nt][3] + b1);
                *(__half2*)(curr + (size_t)(r_ + 8) * HID + c_) = hv;
            }
        }
    }
}

// ======================= output GEMM (tensor cores, fused hop combine) ======
__global__ __launch_bounds__(256)
void gemm_out_mma(const __half* __restrict__ hb,
                  const float* __restrict__ w_s, const float* __restrict__ w_t,
                  const float* __restrict__ Wn, const float* __restrict__ bn,
                  float* __restrict__ out, int M) {
    __shared__ __half Ah[128 * A_STRIDE];
    __shared__ __half Wh[32 * W2_STRIDE];
    int tid = threadIdx.x;
    int lane = tid & 31;
    int warp = tid >> 5;
    int wm = warp >> 1;
    int wn = warp & 1;
    int row0 = blockIdx.x * 128;

    float acc[2][4][4];
    #pragma unroll
    for (int i = 0; i < 2; i++)
        #pragma unroll
        for (int j = 0; j < 4; j++)
            #pragma unroll
            for (int k = 0; k < 4; k++) acc[i][j][k] = 0.f;

    float ws0 = __ldg(w_s + 0), ws1 = __ldg(w_s + 1), ws2 = __ldg(w_s + 2), ws3 = __ldg(w_s + 3);
    float wt0 = __ldg(w_t + 0), wt1 = __ldg(w_t + 1), wt2 = __ldg(w_t + 2), wt3 = __ldg(w_t + 3);

    for (int k0 = 0; k0 < 2 * HID; k0 += 32) {
        int dir = (k0 >= HID);
        const __half* hd = hb + (size_t)(dir * 4) * CAP;
        float w0 = dir ? wt0 : ws0, w1 = dir ? wt1 : ws1;
        float w2 = dir ? wt2 : ws2, w3 = dir ? wt3 : ws3;
        int kc0 = k0 & (HID - 1);

        #pragma unroll
        for (int i = 0; i < 2; i++) {
            int f = tid + i * 256;
            int r = f >> 2;
            int kg = (f & 3) * 8;
            float o[8];
            #pragma unroll
            for (int j = 0; j < 8; j++) o[j] = 0.f;
            if (row0 + r < M) {
                size_t off = (size_t)(row0 + r) * HID + kc0 + kg;
                #pragma unroll
                for (int h = 0; h < 4; h++) {
                    float wh = (h == 0) ? w0 : (h == 1) ? w1 : (h == 2) ? w2 : w3;
                    __half2 hv[4];
                    *(uint4*)hv = *(const uint4*)(hd + h * CAP + off);
                    #pragma unroll
                    for (int j = 0; j < 4; j++) {
                        float2 v = __half22float2(hv[j]);
                        o[2 * j]     += wh * v.x;
                        o[2 * j + 1] += wh * v.y;
                    }
                }
            }
            __half2 oh[4];
            #pragma unroll
            for (int j = 0; j < 4; j++) oh[j] = __floats2half2_rn(o[2 * j], o[2 * j + 1]);
            *(uint4*)&Ah[r * A_STRIDE + kg] = *(uint4*)oh;
        }
        #pragma unroll
        for (int i = 0; i < 2; i++) {
            int f = tid + i * 256;
            int r = f >> 4;
            int cg = (f & 15) * 4;
            float4 v = *(const float4*)(Wn + (size_t)(k0 + r) * NOUT + cg);
            __half2 h0 = __floats2half2_rn(v.x, v.y);
            __half2 h1 = __floats2half2_rn(v.z, v.w);
            *(uint2*)&Wh[r * W2_STRIDE + cg] = make_uint2(*(uint32_t*)&h0, *(uint32_t*)&h1);
        }
        __syncthreads();

        #pragma unroll
        for (int ks = 0; ks < 32; ks += 16) {
            uint32_t aF[2][4];
            #pragma unroll
            for (int mt = 0; mt < 2; mt++) {
                int r = wm * 32 + mt * 16 + (lane & 15);
                int c = ks + ((lane >> 4) << 3);
                ldsm_x4(aF[mt], smem_u32(&Ah[r * A_STRIDE + c]));
            }
            uint32_t bF[2][4];
            #pragma unroll
            for (int ng = 0; ng < 2; ng++) {
                int r = ks + ((lane >> 4) << 3) + (lane & 7);
                int c = wn * 32 + ng * 16 + (((lane >> 3) & 1) << 3);
                ldsm_x4_t(bF[ng], smem_u32(&Wh[r * W2_STRIDE + c]));
            }
            #pragma unroll
            for (int mt = 0; mt < 2; mt++)
                #pragma unroll
                for (int nt = 0; nt < 4; nt++) {
                    int ng = nt >> 1, sel = nt & 1;
                    mma16816(acc[mt][nt], aF[mt], bF[ng][sel], bF[ng][sel + 2]);
                }
        }
        __syncthreads();
    }

    #pragma unroll
    for (int mt = 0; mt < 2; mt++) {
        int r_ = row0 + wm * 32 + mt * 16 + (lane >> 2);
        #pragma unroll
        for (int nt = 0; nt < 4; nt++) {
            int c_ = wn * 32 + nt * 8 + (lane & 3) * 2;
            float b0 = __ldg(bn + c_);
            float b1 = __ldg(bn + c_ + 1);
            if (r_ < M)
                *(float2*)(out + (size_t)r_ * NOUT + c_) =
                    make_float2(acc[mt][nt][0] + b0, acc[mt][nt][1] + b1);
            if (r_ + 8 < M)
                *(float2*)(out + (size_t)(r_ + 8) * NOUT + c_) =
                    make_float2(acc[mt][nt][2] + b0, acc[mt][nt][3] + b1);
        }
    }
}

// ===========================================================================
extern "C" void kernel_launch(void* const* d_in, const int* in_sizes, int n_in,
                              void* d_out, int out_size) {
    const float* fsrc  = (const float*)d_in[0];
    const float* ftgt  = (const float*)d_in[1];
    const int*   erow  = (const int*)d_in[2];
    const int*   ecol  = (const int*)d_in[3];
    const float* ew    = (const float*)d_in[4];
    const float* W_src = (const float*)d_in[5];
    const float* b_src = (const float*)d_in[6];
    const float* W_tgt = (const float*)d_in[7];
    const float* b_tgt = (const float*)d_in[8];
    const float* w_s   = (const float*)d_in[9];
    const float* w_t   = (const float*)d_in[10];
    const float* W_nd  = (const float*)d_in[11];
    const float* b_nd  = (const float*)d_in[12];
    float* out = (float*)d_out;

    int M = in_sizes[0] / FEAT;
    int E = in_sizes[2];

    __half*   hb;     cudaGetSymbolAddress((void**)&hb, g_hbuf);
    int*      deg;    cudaGetSymbolAddress((void**)&deg, g_deg);
    int*      rowptr; cudaGetSymbolAddress((void**)&rowptr, g_rowptr);
    int*      fill;   cudaGetSymbolAddress((void**)&fill, g_fill);
    int*      bsum;   cudaGetSymbolAddress((void**)&bsum, g_bsum);
    uint32_t* csr;    cudaGetSymbolAddress((void**)&csr, g_csr);

    int* deg_s = deg;            int* deg_t = deg + NN;
    int* rp_s  = rowptr;         int* rp_t  = rowptr + (NN + 1);
    int* fil_s = fill;           int* fil_t = fill + NN;
    int* bs_s  = bsum;           int* bs_t  = bsum + 128;
    uint32_t* csr_s = csr;       uint32_t* csr_t = csr + NEDGE;

    int eblocks = (E + 255) / 256;
    int e2blocks = (E + 511) / 512;
    int nchunks = (M + 1023) / 1024;

    // ---- CSR build (both directions) ----
    cudaMemsetAsync(deg_s, 0, 2 * NN * sizeof(int));
    hist_kernel<<<eblocks, 256>>>(erow, ecol, deg_s, deg_t, E);
    {
        dim3 g(nchunks, 2);
        scan_chunk2<<<g, 1024>>>(deg_s, rp_s, bs_s, deg_t, rp_t, bs_t, M);
    }
    {
        dim3 g((M + 256) / 256, 2);
        finalize2<<<g, 256>>>(rp_s, bs_s, fil_s, rp_t, bs_t, fil_t, M, nchunks, E);
    }
    scatter_kernel<<<e2blocks, 256>>>(erow, ecol, ew, fil_s, fil_t, csr_s, csr_t, E);

    // ---- input projections (tensor cores, both in one launch) ----
    {
        dim3 g((M + 127) / 128, 2);
        gemm_input2_mma<<<g, 256>>>(fsrc, W_src, b_src, ftgt, W_tgt, b_tgt, hb, M);
    }

    // ---- hops (both directions per launch) ----
    {
        dim3 g((M * 32 + 255) / 256, 2);
        for (int h = 1; h <= HOPS; h++)
            spmm2_kernel<<<g, 256>>>(rp_s, rp_t, csr_s, csr_t, hb, h, M);
    }

    // ---- output projection (tensor cores, fused hop combine) ----
    gemm_out_mma<<<(M + 127) / 128, 256>>>(hb, w_s, w_t, W_nd, b_nd, out, M);
}

// round 10
// speedup vs baseline: 1.0336x; 1.0336x over previous
#include <cuda_runtime.h>
#include <cuda_fp16.h>
#include <cstddef>
#include <cstdint>

#define NN    100000
#define NEDGE 3200000
#define FEAT  256
#define HID   128
#define NOUT  64
#define HOPS  3
#define CAP   ((size_t)NN * HID)

#define W_SCALE 32767.0f
#define W_INV   (1.0f / 32767.0f)

// 8 fp16 hop buffers: s-dir h0..h3, t-dir h0..h3
__device__ __half    g_hbuf[8][CAP];
__device__ int       g_deg[2][NN];
__device__ int       g_rowptr[2][NN + 1];
__device__ int       g_fill[2][NN];
__device__ int       g_bsum[2][128];
__device__ uint32_t  g_csr[2][NEDGE];   // packed: (nbr << 15) | q15(weight)

// side stream + fork/join events (host objects; created once at load)
static cudaStream_t g_side = 0;
static cudaEvent_t  g_evFork = 0, g_evJoin = 0;
namespace {
struct StreamInit {
    StreamInit() {
        cudaStreamCreateWithFlags(&g_side, cudaStreamNonBlocking);
        cudaEventCreateWithFlags(&g_evFork, cudaEventDisableTiming);
        cudaEventCreateWithFlags(&g_evJoin, cudaEventDisableTiming);
    }
};
static StreamInit g_streamInit;
}

// ======================= CSR build =======================
__global__ __launch_bounds__(256)
void hist_kernel(const int* __restrict__ erow, const int* __restrict__ ecol,
                 int* __restrict__ deg_s, int* __restrict__ deg_t, int E) {
    int e = blockIdx.x * blockDim.x + threadIdx.x;
    if (e < E) {
        atomicAdd(&deg_s[erow[e]], 1);   // no return use -> REDG
        atomicAdd(&deg_t[ecol[e]], 1);
    }
}

// per-1024-chunk exclusive scan + chunk totals; both directions via blockIdx.y
__global__ __launch_bounds__(1024)
void scan_chunk2(const int* __restrict__ deg_s, int* __restrict__ rp_s, int* __restrict__ bs_s,
                 const int* __restrict__ deg_t, int* __restrict__ rp_t, int* __restrict__ bs_t,
                 int n) {
    const int* in = blockIdx.y ? deg_t : deg_s;
    int* out = blockIdx.y ? rp_t : rp_s;
    int* bsum = blockIdx.y ? bs_t : bs_s;
    __shared__ int sh[1024];
    int t = threadIdx.x;
    int g = blockIdx.x * 1024 + t;
    int v = (g < n) ? in[g] : 0;
    sh[t] = v;
    __syncthreads();
    #pragma unroll
    for (int off = 1; off < 1024; off <<= 1) {
        int x = (t >= off) ? sh[t - off] : 0;
        __syncthreads();
        sh[t] += x;
        __syncthreads();
    }
    if (g < n) out[g] = sh[t] - v;         // exclusive within chunk
    if (t == 1023) bsum[blockIdx.x] = sh[1023];
}

// adds chunk prefix (in-block scan over <=128 chunk totals); writes fill too
__global__ __launch_bounds__(256)
void finalize2(int* __restrict__ rp_s, const int* __restrict__ bs_s, int* __restrict__ fil_s,
               int* __restrict__ rp_t, const int* __restrict__ bs_t, int* __restrict__ fil_t,
               int n, int nchunks, int total) {
    int* rowptr = blockIdx.y ? rp_t : rp_s;
    const int* bs = blockIdx.y ? bs_t : bs_s;
    int* fill = blockIdx.y ? fil_t : fil_s;
    __shared__ int sh[128];
    int t = threadIdx.x;
    if (t < 128) sh[t] = (t < nchunks) ? bs[t] : 0;
    __syncthreads();
    #pragma unroll
    for (int off = 1; off < 128; off <<= 1) {
        int x = (t >= off && t < 128) ? sh[t - off] : 0;
        __syncthreads();
        if (t < 128) sh[t] += x;
        __syncthreads();
    }
    int chunk = (blockIdx.x * 256) >> 10;       // constant per block (256 | 1024)
    int pre = chunk ? sh[chunk - 1] : 0;
    int g = blockIdx.x * 256 + t;
    if (g < n) {
        int v = rowptr[g] + pre;
        rowptr[g] = v;
        fill[g] = v;
    }
    if (g == n) rowptr[n] = total;
}

__device__ __forceinline__ void stcs_u32(uint32_t* addr, uint32_t v) {
    asm volatile("st.global.cs.u32 [%0], %1;" :: "l"(addr), "r"(v) : "memory");
}

// 1 edge per thread (measured-best form; scatter is L2-op-throughput bound)
__global__ __launch_bounds__(256)
void scatter_kernel(const int* __restrict__ erow, const int* __restrict__ ecol,
                    const float* __restrict__ ew,
                    int* __restrict__ fill_s, int* __restrict__ fill_t,
                    uint32_t* __restrict__ csr_s, uint32_t* __restrict__ csr_t, int E) {
    int e = blockIdx.x * blockDim.x + threadIdx.x;
    if (e >= E) return;
    int r = erow[e];
    int c = ecol[e];
    uint32_t qw = (uint32_t)__float2int_rn(ew[e] * W_SCALE);
    int ps = atomicAdd(&fill_s[r], 1);
    stcs_u32(csr_s + ps, ((uint32_t)c << 15) | qw);
    int pt = atomicAdd(&fill_t[c], 1);
    stcs_u32(csr_t + pt, ((uint32_t)r << 15) | qw);
}

// ======================= SPMM (fp16 gather, fp32 accumulate) ================
// both directions in one launch; next[i] = fp16( sum_e w_e * x[nbr_e] )
__global__ __launch_bounds__(256)
void spmm2_kernel(const int* __restrict__ rp_s, const int* __restrict__ rp_t,
                  const uint32_t* __restrict__ csr_s, const uint32_t* __restrict__ csr_t,
                  __half* __restrict__ hb, int h, int n) {
    int dir = blockIdx.y;
    const int* rowptr = dir ? rp_t : rp_s;
    const uint32_t* csr = dir ? csr_t : csr_s;
    const __half* x = hb + (size_t)(dir * 4 + h - 1) * CAP;
    __half* next = hb + (size_t)(dir * 4 + h) * CAP;

    int lane = threadIdx.x & 31;
    int node = (int)((blockIdx.x * blockDim.x + threadIdx.x) >> 5);
    if (node >= n) return;
    int beg = rowptr[node];
    int end = rowptr[node + 1];
    float4 acc = make_float4(0.f, 0.f, 0.f, 0.f);
    const uint2* xb = (const uint2*)x + lane;

    int p = beg;
    for (; p + 32 <= end; p += 32) {
        uint32_t pk;
        asm volatile("ld.global.cs.u32 %0, [%1];" : "=r"(pk) : "l"(csr + p + lane));
        #pragma unroll
        for (int j = 0; j < 32; j++) {
            uint32_t pe = __shfl_sync(0xffffffffu, pk, j);
            int   c  = (int)(pe >> 15);
            float wv = (float)(pe & 0x7FFFu) * W_INV;
            uint2 raw = __ldg(xb + (size_t)c * 32);
            float2 v0 = __half22float2(*(__half2*)&raw.x);
            float2 v1 = __half22float2(*(__half2*)&raw.y);
            acc.x = fmaf(wv, v0.x, acc.x);
            acc.y = fmaf(wv, v0.y, acc.y);
            acc.z = fmaf(wv, v1.x, acc.z);
            acc.w = fmaf(wv, v1.y, acc.w);
        }
    }
    int rem = end - p;
    if (rem > 0) {
        uint32_t pk = (lane < rem) ? csr[p + lane] : 0u;
        int j = 0;
        for (; j + 8 <= rem; j += 8) {
            #pragma unroll
            for (int jj = 0; jj < 8; jj++) {
                uint32_t pe = __shfl_sync(0xffffffffu, pk, j + jj);
                int   c  = (int)(pe >> 15);
                float wv = (float)(pe & 0x7FFFu) * W_INV;
                uint2 raw = __ldg(xb + (size_t)c * 32);
                float2 v0 = __half22float2(*(__half2*)&raw.x);
                float2 v1 = __half22float2(*(__half2*)&raw.y);
                acc.x = fmaf(wv, v0.x, acc.x);
                acc.y = fmaf(wv, v0.y, acc.y);
                acc.z = fmaf(wv, v1.x, acc.z);
                acc.w = fmaf(wv, v1.y, acc.w);
            }
        }
        for (; j < rem; j++) {
            uint32_t pe = __shfl_sync(0xffffffffu, pk, j);
            int   c  = (int)(pe >> 15);
            float wv = (float)(pe & 0x7FFFu) * W_INV;
            uint2 raw = __ldg(xb + (size_t)c * 32);
            float2 v0 = __half22float2(*(__half2*)&raw.x);
            float2 v1 = __half22float2(*(__half2*)&raw.y);
            acc.x = fmaf(wv, v0.x, acc.x);
            acc.y = fmaf(wv, v0.y, acc.y);
            acc.z = fmaf(wv, v1.x, acc.z);
            acc.w = fmaf(wv, v1.y, acc.w);
        }
    }

    __half2 o2[2];
    o2[0] = __floats2half2_rn(acc.x, acc.y);
    o2[1] = __floats2half2_rn(acc.z, acc.w);
    *((uint2*)(next + (size_t)node * HID) + lane) = *(uint2*)o2;
}

// ======================= tensor-core helpers ========================
__device__ __forceinline__ uint32_t smem_u32(const void* p) {
    return (uint32_t)__cvta_generic_to_shared(p);
}
__device__ __forceinline__ void ldsm_x4(uint32_t* r, uint32_t addr) {
    asm volatile("ldmatrix.sync.aligned.m8n8.x4.shared.b16 {%0,%1,%2,%3}, [%4];"
                 : "=r"(r[0]), "=r"(r[1]), "=r"(r[2]), "=r"(r[3]) : "r"(addr));
}
__device__ __forceinline__ void ldsm_x4_t(uint32_t* r, uint32_t addr) {
    asm volatile("ldmatrix.sync.aligned.m8n8.x4.trans.shared.b16 {%0,%1,%2,%3}, [%4];"
                 : "=r"(r[0]), "=r"(r[1]), "=r"(r[2]), "=r"(r[3]) : "r"(addr));
}
__device__ __forceinline__ void mma16816(float* c, const uint32_t* a,
                                         uint32_t b0, uint32_t b1) {
    asm volatile("mma.sync.aligned.m16n8k16.row.col.f32.f16.f16.f32 "
                 "{%0,%1,%2,%3}, {%4,%5,%6,%7}, {%8,%9}, {%0,%1,%2,%3};"
                 : "+f"(c[0]), "+f"(c[1]), "+f"(c[2]), "+f"(c[3])
                 : "r"(a[0]), "r"(a[1]), "r"(a[2]), "r"(a[3]), "r"(b0), "r"(b1));
}

#define A_STRIDE 40   // halves per row (32 + 8 pad)
#define W_STRIDE 136  // halves per row (128 + 8 pad)
#define W2_STRIDE 72  // halves per row (64 + 8 pad)

// ======================= input GEMM via tensor cores ========================
// h0 = fp16(A @ W + b); both projections in one launch (blockIdx.y)
__global__ __launch_bounds__(256)
void gemm_input2_mma(const float* __restrict__ A0, const float* __restrict__ W0,
                     const float* __restrict__ bias0,
                     const float* __restrict__ A1, const float* __restrict__ W1,
                     const float* __restrict__ bias1,
                     __half* __restrict__ hb, int M) {
    const float* A    = blockIdx.y ? A1 : A0;
    const float* W    = blockIdx.y ? W1 : W0;
    const float* bias = blockIdx.y ? bias1 : bias0;
    __half* curr = hb + (size_t)(blockIdx.y * 4) * CAP;

    __shared__ __half Ah[128 * A_STRIDE];
    __shared__ __half Wh[32 * W_STRIDE];
    int tid = threadIdx.x;
    int lane = tid & 31;
    int warp = tid >> 5;
    int wm = warp >> 1;
    int wn = warp & 1;
    int row0 = blockIdx.x * 128;

    float acc[2][8][4];
    #pragma unroll
    for (int i = 0; i < 2; i++)
        #pragma unroll
        for (int j = 0; j < 8; j++)
            #pragma unroll
            for (int k = 0; k < 4; k++) acc[i][j][k] = 0.f;

    for (int k0 = 0; k0 < FEAT; k0 += 32) {
        #pragma unroll
        for (int i = 0; i < 4; i++) {
            int f = tid + i * 256;
            int r = f >> 3;
            int cg = (f & 7) * 4;
            float4 v = make_float4(0.f, 0.f, 0.f, 0.f);
            if (row0 + r < M)
                v = *(const float4*)(A + (size_t)(row0 + r) * FEAT + k0 + cg);
            __half2 h0 = __floats2half2_rn(v.x, v.y);
            __half2 h1 = __floats2half2_rn(v.z, v.w);
            *(uint2*)&Ah[r * A_STRIDE + cg] = make_uint2(*(uint32_t*)&h0, *(uint32_t*)&h1);
        }
        #pragma unroll
        for (int i = 0; i < 4; i++) {
            int f = tid + i * 256;
            int r = f >> 5;
            int cg = (f & 31) * 4;
            float4 v = *(const float4*)(W + (size_t)(k0 + r) * HID + cg);
            __half2 h0 = __floats2half2_rn(v.x, v.y);
            __half2 h1 = __floats2half2_rn(v.z, v.w);
            *(uint2*)&Wh[r * W_STRIDE + cg] = make_uint2(*(uint32_t*)&h0, *(uint32_t*)&h1);
        }
        __syncthreads();

        #pragma unroll
        for (int ks = 0; ks < 32; ks += 16) {
            uint32_t aF[2][4];
            #pragma unroll
            for (int mt = 0; mt < 2; mt++) {
                int r = wm * 32 + mt * 16 + (lane & 15);
                int c = ks + ((lane >> 4) << 3);
                ldsm_x4(aF[mt], smem_u32(&Ah[r * A_STRIDE + c]));
            }
            uint32_t bF[4][4];
            #pragma unroll
            for (int ng = 0; ng < 4; ng++) {
                int r = ks + ((lane >> 4) << 3) + (lane & 7);
                int c = wn * 64 + ng * 16 + (((lane >> 3) & 1) << 3);
                ldsm_x4_t(bF[ng], smem_u32(&Wh[r * W_STRIDE + c]));
            }
            #pragma unroll
            for (int mt = 0; mt < 2; mt++)
                #pragma unroll
                for (int nt = 0; nt < 8; nt++) {
                    int ng = nt >> 1, sel = nt & 1;
                    mma16816(acc[mt][nt], aF[mt], bF[ng][sel], bF[ng][sel + 2]);
                }
        }
        __syncthreads();
    }

    #pragma unroll
    for (int mt = 0; mt < 2; mt++) {
        int r_ = row0 + wm * 32 + mt * 16 + (lane >> 2);
        #pragma unroll
        for (int nt = 0; nt < 8; nt++) {
            int c_ = wn * 64 + nt * 8 + (lane & 3) * 2;
            float b0 = __ldg(bias + c_);
            float b1 = __ldg(bias + c_ + 1);
            if (r_ < M) {
                __half2 hv = __floats2half2_rn(acc[mt][nt][0] + b0, acc[mt][nt][1] + b1);
                *(__half2*)(curr + (size_t)r_ * HID + c_) = hv;
            }
            if (r_ + 8 < M) {
                __half2 hv = __floats2half2_rn(acc[mt][nt][2] + b0, acc[mt][nt][3] + b1);
                *(__half2*)(curr + (size_t)(r_ + 8) * HID + c_) = hv;
            }
        }
    }
}

// ======================= output GEMM (tensor cores, fused hop combine) ======
__global__ __launch_bounds__(256)
void gemm_out_mma(const __half* __restrict__ hb,
                  const float* __restrict__ w_s, const float* __restrict__ w_t,
                  const float* __restrict__ Wn, const float* __restrict__ bn,
                  float* __restrict__ out, int M) {
    __shared__ __half Ah[128 * A_STRIDE];
    __shared__ __half Wh[32 * W2_STRIDE];
    int tid = threadIdx.x;
    int lane = tid & 31;
    int warp = tid >> 5;
    int wm = warp >> 1;
    int wn = warp & 1;
    int row0 = blockIdx.x * 128;

    float acc[2][4][4];
    #pragma unroll
    for (int i = 0; i < 2; i++)
        #pragma unroll
        for (int j = 0; j < 4; j++)
            #pragma unroll
            for (int k = 0; k < 4; k++) acc[i][j][k] = 0.f;

    float ws0 = __ldg(w_s + 0), ws1 = __ldg(w_s + 1), ws2 = __ldg(w_s + 2), ws3 = __ldg(w_s + 3);
    float wt0 = __ldg(w_t + 0), wt1 = __ldg(w_t + 1), wt2 = __ldg(w_t + 2), wt3 = __ldg(w_t + 3);

    for (int k0 = 0; k0 < 2 * HID; k0 += 32) {
        int dir = (k0 >= HID);
        const __half* hd = hb + (size_t)(dir * 4) * CAP;
        float w0 = dir ? wt0 : ws0, w1 = dir ? wt1 : ws1;
        float w2 = dir ? wt2 : ws2, w3 = dir ? wt3 : ws3;
        int kc0 = k0 & (HID - 1);

        #pragma unroll
        for (int i = 0; i < 2; i++) {
            int f = tid + i * 256;
            int r = f >> 2;
            int kg = (f & 3) * 8;
            float o[8];
            #pragma unroll
            for (int j = 0; j < 8; j++) o[j] = 0.f;
            if (row0 + r < M) {
                size_t off = (size_t)(row0 + r) * HID + kc0 + kg;
                #pragma unroll
                for (int h = 0; h < 4; h++) {
                    float wh = (h == 0) ? w0 : (h == 1) ? w1 : (h == 2) ? w2 : w3;
                    __half2 hv[4];
                    *(uint4*)hv = *(const uint4*)(hd + h * CAP + off);
                    #pragma unroll
                    for (int j = 0; j < 4; j++) {
                        float2 v = __half22float2(hv[j]);
                        o[2 * j]     += wh * v.x;
                        o[2 * j + 1] += wh * v.y;
                    }
                }
            }
            __half2 oh[4];
            #pragma unroll
            for (int j = 0; j < 4; j++) oh[j] = __floats2half2_rn(o[2 * j], o[2 * j + 1]);
            *(uint4*)&Ah[r * A_STRIDE + kg] = *(uint4*)oh;
        }
        #pragma unroll
        for (int i = 0; i < 2; i++) {
            int f = tid + i * 256;
            int r = f >> 4;
            int cg = (f & 15) * 4;
            float4 v = *(const float4*)(Wn + (size_t)(k0 + r) * NOUT + cg);
            __half2 h0 = __floats2half2_rn(v.x, v.y);
            __half2 h1 = __floats2half2_rn(v.z, v.w);
            *(uint2*)&Wh[r * W2_STRIDE + cg] = make_uint2(*(uint32_t*)&h0, *(uint32_t*)&h1);
        }
        __syncthreads();

        #pragma unroll
        for (int ks = 0; ks < 32; ks += 16) {
            uint32_t aF[2][4];
            #pragma unroll
            for (int mt = 0; mt < 2; mt++) {
                int r = wm * 32 + mt * 16 + (lane & 15);
                int c = ks + ((lane >> 4) << 3);
                ldsm_x4(aF[mt], smem_u32(&Ah[r * A_STRIDE + c]));
            }
            uint32_t bF[2][4];
            #pragma unroll
            for (int ng = 0; ng < 2; ng++) {
                int r = ks + ((lane >> 4) << 3) + (lane & 7);
                int c = wn * 32 + ng * 16 + (((lane >> 3) & 1) << 3);
                ldsm_x4_t(bF[ng], smem_u32(&Wh[r * W2_STRIDE + c]));
            }
            #pragma unroll
            for (int mt = 0; mt < 2; mt++)
                #pragma unroll
                for (int nt = 0; nt < 4; nt++) {
                    int ng = nt >> 1, sel = nt & 1;
                    mma16816(acc[mt][nt], aF[mt], bF[ng][sel], bF[ng][sel + 2]);
                }
        }
        __syncthreads();
    }

    #pragma unroll
    for (int mt = 0; mt < 2; mt++) {
        int r_ = row0 + wm * 32 + mt * 16 + (lane >> 2);
        #pragma unroll
        for (int nt = 0; nt < 4; nt++) {
            int c_ = wn * 32 + nt * 8 + (lane & 3) * 2;
            float b0 = __ldg(bn + c_);
            float b1 = __ldg(bn + c_ + 1);
            if (r_ < M)
                *(float2*)(out + (size_t)r_ * NOUT + c_) =
                    make_float2(acc[mt][nt][0] + b0, acc[mt][nt][1] + b1);
            if (r_ + 8 < M)
                *(float2*)(out + (size_t)(r_ + 8) * NOUT + c_) =
                    make_float2(acc[mt][nt][2] + b0, acc[mt][nt][3] + b1);
        }
    }
}

// ===========================================================================
extern "C" void kernel_launch(void* const* d_in, const int* in_sizes, int n_in,
                              void* d_out, int out_size) {
    const float* fsrc  = (const float*)d_in[0];
    const float* ftgt  = (const float*)d_in[1];
    const int*   erow  = (const int*)d_in[2];
    const int*   ecol  = (const int*)d_in[3];
    const float* ew    = (const float*)d_in[4];
    const float* W_src = (const float*)d_in[5];
    const float* b_src = (const float*)d_in[6];
    const float* W_tgt = (const float*)d_in[7];
    const float* b_tgt = (const float*)d_in[8];
    const float* w_s   = (const float*)d_in[9];
    const float* w_t   = (const float*)d_in[10];
    const float* W_nd  = (const float*)d_in[11];
    const float* b_nd  = (const float*)d_in[12];
    float* out = (float*)d_out;

    int M = in_sizes[0] / FEAT;
    int E = in_sizes[2];

    __half*   hb;     cudaGetSymbolAddress((void**)&hb, g_hbuf);
    int*      deg;    cudaGetSymbolAddress((void**)&deg, g_deg);
    int*      rowptr; cudaGetSymbolAddress((void**)&rowptr, g_rowptr);
    int*      fill;   cudaGetSymbolAddress((void**)&fill, g_fill);
    int*      bsum;   cudaGetSymbolAddress((void**)&bsum, g_bsum);
    uint32_t* csr;    cudaGetSymbolAddress((void**)&csr, g_csr);

    int* deg_s = deg;            int* deg_t = deg + NN;
    int* rp_s  = rowptr;         int* rp_t  = rowptr + (NN + 1);
    int* fil_s = fill;           int* fil_t = fill + NN;
    int* bs_s  = bsum;           int* bs_t  = bsum + 128;
    uint32_t* csr_s = csr;       uint32_t* csr_t = csr + NEDGE;

    int eblocks = (E + 255) / 256;
    int nchunks = (M + 1023) / 1024;

    bool fork = (g_side != 0 && g_evFork != 0 && g_evJoin != 0);
    cudaStream_t cs = fork ? g_side : 0;   // CSR-chain stream

    if (fork) {
        cudaEventRecord(g_evFork, 0);
        cudaStreamWaitEvent(g_side, g_evFork, 0);
    }

    // ---- CSR build (side stream) ----
    cudaMemsetAsync(deg_s, 0, 2 * NN * sizeof(int), cs);
    hist_kernel<<<eblocks, 256, 0, cs>>>(erow, ecol, deg_s, deg_t, E);
    {
        dim3 g(nchunks, 2);
        scan_chunk2<<<g, 1024, 0, cs>>>(deg_s, rp_s, bs_s, deg_t, rp_t, bs_t, M);
    }
    {
        dim3 g((M + 256) / 256, 2);
        finalize2<<<g, 256, 0, cs>>>(rp_s, bs_s, fil_s, rp_t, bs_t, fil_t, M, nchunks, E);
    }
    scatter_kernel<<<eblocks, 256, 0, cs>>>(erow, ecol, ew, fil_s, fil_t, csr_s, csr_t, E);

    // ---- input projections (main stream, overlapped with CSR build) ----
    {
        dim3 g((M + 127) / 128, 2);
        gemm_input2_mma<<<g, 256>>>(fsrc, W_src, b_src, ftgt, W_tgt, b_tgt, hb, M);
    }

    if (fork) {
        cudaEventRecord(g_evJoin, g_side);
        cudaStreamWaitEvent(0, g_evJoin, 0);
    }

    // ---- hops (both directions per launch) ----
    {
        dim3 g((M * 32 + 255) / 256, 2);
        for (int h = 1; h <= HOPS; h++)
            spmm2_kernel<<<g, 256>>>(rp_s, rp_t, csr_s, csr_t, hb, h, M);
    }

    // ---- output projection (tensor cores, fused hop combine) ----
    gemm_out_mma<<<(M + 127) / 128, 256>>>(hb, w_s, w_t, W_nd, b_nd, out, M);
}

// round 11
// speedup vs baseline: 1.0395x; 1.0057x over previous
#include <cuda_runtime.h>
#include <cuda_fp16.h>
#include <cstddef>
#include <cstdint>

#define NN    100000
#define NEDGE 3200000
#define FEAT  256
#define HID   128
#define NOUT  64
#define HOPS  3
#define CAP   ((size_t)NN * HID)

#define W_SCALE 32767.0f
#define W_INV   (1.0f / 32767.0f)

// 8 fp16 hop buffers: s-dir h0..h3, t-dir h0..h3
__device__ __half    g_hbuf[8][CAP];
__device__ int       g_deg[2][NN];
__device__ int       g_rowptr[2][NN + 1];
__device__ int       g_fill[2][NN];
__device__ int       g_bsum[2][128];
__device__ uint32_t  g_csr[2][NEDGE];   // packed: (nbr << 15) | q15(weight)

// side stream + fork/join events (host objects; created once at load)
static cudaStream_t g_side = 0;
static cudaEvent_t  g_evFork = 0, g_evJoin = 0;
namespace {
struct StreamInit {
    StreamInit() {
        cudaStreamCreateWithFlags(&g_side, cudaStreamNonBlocking);
        cudaEventCreateWithFlags(&g_evFork, cudaEventDisableTiming);
        cudaEventCreateWithFlags(&g_evJoin, cudaEventDisableTiming);
    }
};
static StreamInit g_streamInit;
}

// ======================= CSR build =======================
__global__ __launch_bounds__(256)
void hist_kernel(const int* __restrict__ erow, const int* __restrict__ ecol,
                 int* __restrict__ deg_s, int* __restrict__ deg_t, int E) {
    int e = blockIdx.x * blockDim.x + threadIdx.x;
    if (e < E) {
        atomicAdd(&deg_s[erow[e]], 1);   // no return use -> REDG
        atomicAdd(&deg_t[ecol[e]], 1);
    }
}

__global__ __launch_bounds__(1024)
void scan_chunk2(const int* __restrict__ deg_s, int* __restrict__ rp_s, int* __restrict__ bs_s,
                 const int* __restrict__ deg_t, int* __restrict__ rp_t, int* __restrict__ bs_t,
                 int n) {
    const int* in = blockIdx.y ? deg_t : deg_s;
    int* out = blockIdx.y ? rp_t : rp_s;
    int* bsum = blockIdx.y ? bs_t : bs_s;
    __shared__ int sh[1024];
    int t = threadIdx.x;
    int g = blockIdx.x * 1024 + t;
    int v = (g < n) ? in[g] : 0;
    sh[t] = v;
    __syncthreads();
    #pragma unroll
    for (int off = 1; off < 1024; off <<= 1) {
        int x = (t >= off) ? sh[t - off] : 0;
        __syncthreads();
        sh[t] += x;
        __syncthreads();
    }
    if (g < n) out[g] = sh[t] - v;         // exclusive within chunk
    if (t == 1023) bsum[blockIdx.x] = sh[1023];
}

__global__ __launch_bounds__(256)
void finalize2(int* __restrict__ rp_s, const int* __restrict__ bs_s, int* __restrict__ fil_s,
               int* __restrict__ rp_t, const int* __restrict__ bs_t, int* __restrict__ fil_t,
               int n, int nchunks, int total) {
    int* rowptr = blockIdx.y ? rp_t : rp_s;
    const int* bs = blockIdx.y ? bs_t : bs_s;
    int* fill = blockIdx.y ? fil_t : fil_s;
    __shared__ int sh[128];
    int t = threadIdx.x;
    if (t < 128) sh[t] = (t < nchunks) ? bs[t] : 0;
    __syncthreads();
    #pragma unroll
    for (int off = 1; off < 128; off <<= 1) {
        int x = (t >= off && t < 128) ? sh[t - off] : 0;
        __syncthreads();
        if (t < 128) sh[t] += x;
        __syncthreads();
    }
    int chunk = (blockIdx.x * 256) >> 10;
    int pre = chunk ? sh[chunk - 1] : 0;
    int g = blockIdx.x * 256 + t;
    if (g < n) {
        int v = rowptr[g] + pre;
        rowptr[g] = v;
        fill[g] = v;
    }
    if (g == n) rowptr[n] = total;
}

__device__ __forceinline__ void stcs_u32(uint32_t* addr, uint32_t v) {
    asm volatile("st.global.cs.u32 [%0], %1;" :: "l"(addr), "r"(v) : "memory");
}

// 1 edge per thread (measured-best form; scatter is L2-op-throughput bound)
__global__ __launch_bounds__(256)
void scatter_kernel(const int* __restrict__ erow, const int* __restrict__ ecol,
                    const float* __restrict__ ew,
                    int* __restrict__ fill_s, int* __restrict__ fill_t,
                    uint32_t* __restrict__ csr_s, uint32_t* __restrict__ csr_t, int E) {
    int e = blockIdx.x * blockDim.x + threadIdx.x;
    if (e >= E) return;
    int r = erow[e];
    int c = ecol[e];
    uint32_t qw = (uint32_t)__float2int_rn(ew[e] * W_SCALE);
    int ps = atomicAdd(&fill_s[r], 1);
    stcs_u32(csr_s + ps, ((uint32_t)c << 15) | qw);
    int pt = atomicAdd(&fill_t[c], 1);
    stcs_u32(csr_t + pt, ((uint32_t)r << 15) | qw);
}

// ======================= SPMM (fp16 gather, fp32 accumulate) ================
// HALF-WARP per node: 16 lanes x 16B = 256B row; 2 nodes per warp.
// Per group: batches of 16 CSR entries, shfl-broadcast; per-group predication.
__global__ __launch_bounds__(256)
void spmm2_kernel(const int* __restrict__ rp_s, const int* __restrict__ rp_t,
                  const uint32_t* __restrict__ csr_s, const uint32_t* __restrict__ csr_t,
                  __half* __restrict__ hb, int h, int n) {
    int dir = blockIdx.y;
    const int* rowptr = dir ? rp_t : rp_s;
    const uint32_t* csr = dir ? csr_t : csr_s;
    const __half* x = hb + (size_t)(dir * 4 + h - 1) * CAP;
    __half* next = hb + (size_t)(dir * 4 + h) * CAP;

    int lane  = threadIdx.x & 31;
    int half  = lane >> 4;          // group 0 / group 1
    int hlane = lane & 15;
    int pairw = (int)((blockIdx.x * blockDim.x + threadIdx.x) >> 5);
    int node  = pairw * 2 + half;
    bool valid = (node < n);

    int beg = valid ? rowptr[node] : 0;
    int end = valid ? rowptr[node + 1] : 0;

    float acc[8];
    #pragma unroll
    for (int i = 0; i < 8; i++) acc[i] = 0.f;

    const uint4* xb = (const uint4*)x + hlane;   // row stride = 16 uint4

    int p = beg;
    while (true) {
        int cnt = end - p;
        if (cnt > 16) cnt = 16;
        unsigned any = __ballot_sync(0xffffffffu, cnt > 0);
        if (!any) break;
        uint32_t pk = 0;
        if (hlane < cnt) {
            asm volatile("ld.global.cs.u32 %0, [%1];" : "=r"(pk) : "l"(csr + p + hlane));
        }
        #pragma unroll
        for (int j = 0; j < 16; j++) {
            uint32_t pe = __shfl_sync(0xffffffffu, pk, (half << 4) + j);
            if (j < cnt) {
                int   c  = (int)(pe >> 15);
                float wv = (float)(pe & 0x7FFFu) * W_INV;
                uint4 raw = __ldg(xb + (size_t)c * 16);
                float2 v0 = __half22float2(*(__half2*)&raw.x);
                float2 v1 = __half22float2(*(__half2*)&raw.y);
                float2 v2 = __half22float2(*(__half2*)&raw.z);
                float2 v3 = __half22float2(*(__half2*)&raw.w);
                acc[0] = fmaf(wv, v0.x, acc[0]);
                acc[1] = fmaf(wv, v0.y, acc[1]);
                acc[2] = fmaf(wv, v1.x, acc[2]);
                acc[3] = fmaf(wv, v1.y, acc[3]);
                acc[4] = fmaf(wv, v2.x, acc[4]);
                acc[5] = fmaf(wv, v2.y, acc[5]);
                acc[6] = fmaf(wv, v3.x, acc[6]);
                acc[7] = fmaf(wv, v3.y, acc[7]);
            }
        }
        p += cnt;
    }

    if (valid) {
        __half2 o[4];
        o[0] = __floats2half2_rn(acc[0], acc[1]);
        o[1] = __floats2half2_rn(acc[2], acc[3]);
        o[2] = __floats2half2_rn(acc[4], acc[5]);
        o[3] = __floats2half2_rn(acc[6], acc[7]);
        *((uint4*)(next + (size_t)node * HID) + hlane) = *(uint4*)o;
    }
}

// ======================= tensor-core helpers ========================
__device__ __forceinline__ uint32_t smem_u32(const void* p) {
    return (uint32_t)__cvta_generic_to_shared(p);
}
__device__ __forceinline__ void ldsm_x4(uint32_t* r, uint32_t addr) {
    asm volatile("ldmatrix.sync.aligned.m8n8.x4.shared.b16 {%0,%1,%2,%3}, [%4];"
                 : "=r"(r[0]), "=r"(r[1]), "=r"(r[2]), "=r"(r[3]) : "r"(addr));
}
__device__ __forceinline__ void ldsm_x4_t(uint32_t* r, uint32_t addr) {
    asm volatile("ldmatrix.sync.aligned.m8n8.x4.trans.shared.b16 {%0,%1,%2,%3}, [%4];"
                 : "=r"(r[0]), "=r"(r[1]), "=r"(r[2]), "=r"(r[3]) : "r"(addr));
}
__device__ __forceinline__ void mma16816(float* c, const uint32_t* a,
                                         uint32_t b0, uint32_t b1) {
    asm volatile("mma.sync.aligned.m16n8k16.row.col.f32.f16.f16.f32 "
                 "{%0,%1,%2,%3}, {%4,%5,%6,%7}, {%8,%9}, {%0,%1,%2,%3};"
                 : "+f"(c[0]), "+f"(c[1]), "+f"(c[2]), "+f"(c[3])
                 : "r"(a[0]), "r"(a[1]), "r"(a[2]), "r"(a[3]), "r"(b0), "r"(b1));
}

#define A_STRIDE 40   // halves per row (32 + 8 pad)
#define W_STRIDE 136  // halves per row (128 + 8 pad)
#define W2_STRIDE 72  // halves per row (64 + 8 pad)

// ======================= input GEMM via tensor cores ========================
__global__ __launch_bounds__(256)
void gemm_input2_mma(const float* __restrict__ A0, const float* __restrict__ W0,
                     const float* __restrict__ bias0,
                     const float* __restrict__ A1, const float* __restrict__ W1,
                     const float* __restrict__ bias1,
                     __half* __restrict__ hb, int M) {
    const float* A    = blockIdx.y ? A1 : A0;
    const float* W    = blockIdx.y ? W1 : W0;
    const float* bias = blockIdx.y ? bias1 : bias0;
    __half* curr = hb + (size_t)(blockIdx.y * 4) * CAP;

    __shared__ __half Ah[128 * A_STRIDE];
    __shared__ __half Wh[32 * W_STRIDE];
    int tid = threadIdx.x;
    int lane = tid & 31;
    int warp = tid >> 5;
    int wm = warp >> 1;
    int wn = warp & 1;
    int row0 = blockIdx.x * 128;

    float acc[2][8][4];
    #pragma unroll
    for (int i = 0; i < 2; i++)
        #pragma unroll
        for (int j = 0; j < 8; j++)
            #pragma unroll
            for (int k = 0; k < 4; k++) acc[i][j][k] = 0.f;

    for (int k0 = 0; k0 < FEAT; k0 += 32) {
        #pragma unroll
        for (int i = 0; i < 4; i++) {
            int f = tid + i * 256;
            int r = f >> 3;
            int cg = (f & 7) * 4;
            float4 v = make_float4(0.f, 0.f, 0.f, 0.f);
            if (row0 + r < M)
                v = *(const float4*)(A + (size_t)(row0 + r) * FEAT + k0 + cg);
            __half2 h0 = __floats2half2_rn(v.x, v.y);
            __half2 h1 = __floats2half2_rn(v.z, v.w);
            *(uint2*)&Ah[r * A_STRIDE + cg] = make_uint2(*(uint32_t*)&h0, *(uint32_t*)&h1);
        }
        #pragma unroll
        for (int i = 0; i < 4; i++) {
            int f = tid + i * 256;
            int r = f >> 5;
            int cg = (f & 31) * 4;
            float4 v = *(const float4*)(W + (size_t)(k0 + r) * HID + cg);
            __half2 h0 = __floats2half2_rn(v.x, v.y);
            __half2 h1 = __floats2half2_rn(v.z, v.w);
            *(uint2*)&Wh[r * W_STRIDE + cg] = make_uint2(*(uint32_t*)&h0, *(uint32_t*)&h1);
        }
        __syncthreads();

        #pragma unroll
        for (int ks = 0; ks < 32; ks += 16) {
            uint32_t aF[2][4];
            #pragma unroll
            for (int mt = 0; mt < 2; mt++) {
                int r = wm * 32 + mt * 16 + (lane & 15);
                int c = ks + ((lane >> 4) << 3);
                ldsm_x4(aF[mt], smem_u32(&Ah[r * A_STRIDE + c]));
            }
            uint32_t bF[4][4];
            #pragma unroll
            for (int ng = 0; ng < 4; ng++) {
                int r = ks + ((lane >> 4) << 3) + (lane & 7);
                int c = wn * 64 + ng * 16 + (((lane >> 3) & 1) << 3);
                ldsm_x4_t(bF[ng], smem_u32(&Wh[r * W_STRIDE + c]));
            }
            #pragma unroll
            for (int mt = 0; mt < 2; mt++)
                #pragma unroll
                for (int nt = 0; nt < 8; nt++) {
                    int ng = nt >> 1, sel = nt & 1;
                    mma16816(acc[mt][nt], aF[mt], bF[ng][sel], bF[ng][sel + 2]);
                }
        }
        __syncthreads();
    }

    #pragma unroll
    for (int mt = 0; mt < 2; mt++) {
        int r_ = row0 + wm * 32 + mt * 16 + (lane >> 2);
        #pragma unroll
        for (int nt = 0; nt < 8; nt++) {
            int c_ = wn * 64 + nt * 8 + (lane & 3) * 2;
            float b0 = __ldg(bias + c_);
            float b1 = __ldg(bias + c_ + 1);
            if (r_ < M) {
                __half2 hv = __floats2half2_rn(acc[mt][nt][0] + b0, acc[mt][nt][1] + b1);
                *(__half2*)(curr + (size_t)r_ * HID + c_) = hv;
            }
            if (r_ + 8 < M) {
                __half2 hv = __floats2half2_rn(acc[mt][nt][2] + b0, acc[mt][nt][3] + b1);
                *(__half2*)(curr + (size_t)(r_ + 8) * HID + c_) = hv;
            }
        }
    }
}

// ======================= output GEMM (tensor cores, fused hop combine) ======
__global__ __launch_bounds__(256)
void gemm_out_mma(const __half* __restrict__ hb,
                  const float* __restrict__ w_s, const float* __restrict__ w_t,
                  const float* __restrict__ Wn, const float* __restrict__ bn,
                  float* __restrict__ out, int M) {
    __shared__ __half Ah[128 * A_STRIDE];
    __shared__ __half Wh[32 * W2_STRIDE];
    int tid = threadIdx.x;
    int lane = tid & 31;
    int warp = tid >> 5;
    int wm = warp >> 1;
    int wn = warp & 1;
    int row0 = blockIdx.x * 128;

    float acc[2][4][4];
    #pragma unroll
    for (int i = 0; i < 2; i++)
        #pragma unroll
        for (int j = 0; j < 4; j++)
            #pragma unroll
            for (int k = 0; k < 4; k++) acc[i][j][k] = 0.f;

    float ws0 = __ldg(w_s + 0), ws1 = __ldg(w_s + 1), ws2 = __ldg(w_s + 2), ws3 = __ldg(w_s + 3);
    float wt0 = __ldg(w_t + 0), wt1 = __ldg(w_t + 1), wt2 = __ldg(w_t + 2), wt3 = __ldg(w_t + 3);

    for (int k0 = 0; k0 < 2 * HID; k0 += 32) {
        int dir = (k0 >= HID);
        const __half* hd = hb + (size_t)(dir * 4) * CAP;
        float w0 = dir ? wt0 : ws0, w1 = dir ? wt1 : ws1;
        float w2 = dir ? wt2 : ws2, w3 = dir ? wt3 : ws3;
        int kc0 = k0 & (HID - 1);

        #pragma unroll
        for (int i = 0; i < 2; i++) {
            int f = tid + i * 256;
            int r = f >> 2;
            int kg = (f & 3) * 8;
            float o[8];
            #pragma unroll
            for (int j = 0; j < 8; j++) o[j] = 0.f;
            if (row0 + r < M) {
                size_t off = (size_t)(row0 + r) * HID + kc0 + kg;
                #pragma unroll
                for (int h = 0; h < 4; h++) {
                    float wh = (h == 0) ? w0 : (h == 1) ? w1 : (h == 2) ? w2 : w3;
                    __half2 hv[4];
                    *(uint4*)hv = *(const uint4*)(hd + h * CAP + off);
                    #pragma unroll
                    for (int j = 0; j < 4; j++) {
                        float2 v = __half22float2(hv[j]);
                        o[2 * j]     += wh * v.x;
                        o[2 * j + 1] += wh * v.y;
                    }
                }
            }
            __half2 oh[4];
            #pragma unroll
            for (int j = 0; j < 4; j++) oh[j] = __floats2half2_rn(o[2 * j], o[2 * j + 1]);
            *(uint4*)&Ah[r * A_STRIDE + kg] = *(uint4*)oh;
        }
        #pragma unroll
        for (int i = 0; i < 2; i++) {
            int f = tid + i * 256;
            int r = f >> 4;
            int cg = (f & 15) * 4;
            float4 v = *(const float4*)(Wn + (size_t)(k0 + r) * NOUT + cg);
            __half2 h0 = __floats2half2_rn(v.x, v.y);
            __half2 h1 = __floats2half2_rn(v.z, v.w);
            *(uint2*)&Wh[r * W2_STRIDE + cg] = make_uint2(*(uint32_t*)&h0, *(uint32_t*)&h1);
        }
        __syncthreads();

        #pragma unroll
        for (int ks = 0; ks < 32; ks += 16) {
            uint32_t aF[2][4];
            #pragma unroll
            for (int mt = 0; mt < 2; mt++) {
                int r = wm * 32 + mt * 16 + (lane & 15);
                int c = ks + ((lane >> 4) << 3);
                ldsm_x4(aF[mt], smem_u32(&Ah[r * A_STRIDE + c]));
            }
            uint32_t bF[2][4];
            #pragma unroll
            for (int ng = 0; ng < 2; ng++) {
                int r = ks + ((lane >> 4) << 3) + (lane & 7);
                int c = wn * 32 + ng * 16 + (((lane >> 3) & 1) << 3);
                ldsm_x4_t(bF[ng], smem_u32(&Wh[r * W2_STRIDE + c]));
            }
            #pragma unroll
            for (int mt = 0; mt < 2; mt++)
                #pragma unroll
                for (int nt = 0; nt < 4; nt++) {
                    int ng = nt >> 1, sel = nt & 1;
                    mma16816(acc[mt][nt], aF[mt], bF[ng][sel], bF[ng][sel + 2]);
                }
        }
        __syncthreads();
    }

    #pragma unroll
    for (int mt = 0; mt < 2; mt++) {
        int r_ = row0 + wm * 32 + mt * 16 + (lane >> 2);
        #pragma unroll
        for (int nt = 0; nt < 4; nt++) {
            int c_ = wn * 32 + nt * 8 + (lane & 3) * 2;
            float b0 = __ldg(bn + c_);
            float b1 = __ldg(bn + c_ + 1);
            if (r_ < M)
                *(float2*)(out + (size_t)r_ * NOUT + c_) =
                    make_float2(acc[mt][nt][0] + b0, acc[mt][nt][1] + b1);
            if (r_ + 8 < M)
                *(float2*)(out + (size_t)(r_ + 8) * NOUT + c_) =
                    make_float2(acc[mt][nt][2] + b0, acc[mt][nt][3] + b1);
        }
    }
}

// ===========================================================================
extern "C" void kernel_launch(void* const* d_in, const int* in_sizes, int n_in,
                              void* d_out, int out_size) {
    const float* fsrc  = (const float*)d_in[0];
    const float* ftgt  = (const float*)d_in[1];
    const int*   erow  = (const int*)d_in[2];
    const int*   ecol  = (const int*)d_in[3];
    const float* ew    = (const float*)d_in[4];
    const float* W_src = (const float*)d_in[5];
    const float* b_src = (const float*)d_in[6];
    const float* W_tgt = (const float*)d_in[7];
    const float* b_tgt = (const float*)d_in[8];
    const float* w_s   = (const float*)d_in[9];
    const float* w_t   = (const float*)d_in[10];
    const float* W_nd  = (const float*)d_in[11];
    const float* b_nd  = (const float*)d_in[12];
    float* out = (float*)d_out;

    int M = in_sizes[0] / FEAT;
    int E = in_sizes[2];

    __half*   hb;     cudaGetSymbolAddress((void**)&hb, g_hbuf);
    int*      deg;    cudaGetSymbolAddress((void**)&deg, g_deg);
    int*      rowptr; cudaGetSymbolAddress((void**)&rowptr, g_rowptr);
    int*      fill;   cudaGetSymbolAddress((void**)&fill, g_fill);
    int*      bsum;   cudaGetSymbolAddress((void**)&bsum, g_bsum);
    uint32_t* csr;    cudaGetSymbolAddress((void**)&csr, g_csr);

    int* deg_s = deg;            int* deg_t = deg + NN;
    int* rp_s  = rowptr;         int* rp_t  = rowptr + (NN + 1);
    int* fil_s = fill;           int* fil_t = fill + NN;
    int* bs_s  = bsum;           int* bs_t  = bsum + 128;
    uint32_t* csr_s = csr;       uint32_t* csr_t = csr + NEDGE;

    int eblocks = (E + 255) / 256;
    int nchunks = (M + 1023) / 1024;

    bool fork = (g_side != 0 && g_evFork != 0 && g_evJoin != 0);
    cudaStream_t cs = fork ? g_side : 0;

    if (fork) {
        cudaEventRecord(g_evFork, 0);
        cudaStreamWaitEvent(g_side, g_evFork, 0);
    }

    // ---- CSR build (side stream) ----
    cudaMemsetAsync(deg_s, 0, 2 * NN * sizeof(int), cs);
    hist_kernel<<<eblocks, 256, 0, cs>>>(erow, ecol, deg_s, deg_t, E);
    {
        dim3 g(nchunks, 2);
        scan_chunk2<<<g, 1024, 0, cs>>>(deg_s, rp_s, bs_s, deg_t, rp_t, bs_t, M);
    }
    {
        dim3 g((M + 256) / 256, 2);
        finalize2<<<g, 256, 0, cs>>>(rp_s, bs_s, fil_s, rp_t, bs_t, fil_t, M, nchunks, E);
    }
    scatter_kernel<<<eblocks, 256, 0, cs>>>(erow, ecol, ew, fil_s, fil_t, csr_s, csr_t, E);

    // ---- input projections (main stream, overlapped with CSR build) ----
    {
        dim3 g((M + 127) / 128, 2);
        gemm_input2_mma<<<g, 256>>>(fsrc, W_src, b_src, ftgt, W_tgt, b_tgt, hb, M);
    }

    if (fork) {
        cudaEventRecord(g_evJoin, g_side);
        cudaStreamWaitEvent(0, g_evJoin, 0);
    }

    // ---- hops (both directions per launch; 2 nodes per warp) ----
    {
        int warps = (M + 1) / 2;                    // one warp per node-pair
        dim3 g((warps * 32 + 255) / 256, 2);
        for (int h = 1; h <= HOPS; h++)
            spmm2_kernel<<<g, 256>>>(rp_s, rp_t, csr_s, csr_t, hb, h, M);
    }

    // ---- output projection (tensor cores, fused hop combine) ----
    gemm_out_mma<<<(M + 127) / 128, 256>>>(hb, w_s, w_t, W_nd, b_nd, out, M);
}

// round 13
// speedup vs baseline: 1.4657x; 1.4100x over previous
#include <cuda_runtime.h>
#include <cuda_fp16.h>
#include <cstddef>
#include <cstdint>

#define NN    100000
#define NEDGE 3200000
#define FEAT  256
#define HID   128
#define NOUT  64
#define HOPS  3
#define CAPO  ((size_t)NN * NOUT)

#define W_SCALE 32767.0f
#define W_INV   (1.0f / 32767.0f)

// 8 fp16 hop buffers (64-dim): s-dir y0..y3, t-dir y0..y3
__device__ __half    g_hbuf[8][CAPO];
__device__ int       g_deg[2][NN];
__device__ int       g_rowptr[2][NN + 1];
__device__ int       g_fill[2][NN];
__device__ int       g_bsum[2][128];
__device__ uint32_t  g_csr[2][NEDGE];   // packed: (nbr << 15) | q15(weight)
__device__ float     g_wc[2][FEAT][NOUT];   // folded W_in @ Wn_half
__device__ float     g_bc[2][NOUT];         // folded b_in @ Wn_half

// side stream + fork/join events (host objects; created once at load)
static cudaStream_t g_side = 0;
static cudaEvent_t  g_evFork = 0, g_evJoin = 0;
namespace {
struct StreamInit {
    StreamInit() {
        cudaStreamCreateWithFlags(&g_side, cudaStreamNonBlocking);
        cudaEventCreateWithFlags(&g_evFork, cudaEventDisableTiming);
        cudaEventCreateWithFlags(&g_evJoin, cudaEventDisableTiming);
    }
};
static StreamInit g_streamInit;
}

// ======================= weight folding =======================
// Wc[dir] = W_in[dir] @ Wn[dir*HID : dir*HID+HID, :]   (fp32, exact fold)
__global__ __launch_bounds__(64)
void fold_kernel(const float* __restrict__ W_src, const float* __restrict__ b_src,
                 const float* __restrict__ W_tgt, const float* __restrict__ b_tgt,
                 const float* __restrict__ Wn, float* __restrict__ wc,
                 float* __restrict__ bc) {
    int dir = blockIdx.y;
    int i = blockIdx.x;          // 0..FEAT; FEAT => bias row
    int j = threadIdx.x;         // 0..63
    const float* W = dir ? W_tgt : W_src;
    const float* b = dir ? b_tgt : b_src;
    float acc = 0.f;
    if (i < FEAT) {
        for (int k = 0; k < HID; k++)
            acc += W[i * HID + k] * Wn[(size_t)(dir * HID + k) * NOUT + j];
        wc[(size_t)dir * FEAT * NOUT + (size_t)i * NOUT + j] = acc;
    } else {
        for (int k = 0; k < HID; k++)
            acc += b[k] * Wn[(size_t)(dir * HID + k) * NOUT + j];
        bc[dir * NOUT + j] = acc;
    }
}

// ======================= CSR build =======================
__global__ __launch_bounds__(256)
void hist_kernel(const int* __restrict__ erow, const int* __restrict__ ecol,
                 int* __restrict__ deg_s, int* __restrict__ deg_t, int E) {
    int e = blockIdx.x * blockDim.x + threadIdx.x;
    if (e < E) {
        atomicAdd(&deg_s[erow[e]], 1);
        atomicAdd(&deg_t[ecol[e]], 1);
    }
}

__global__ __launch_bounds__(1024)
void scan_chunk2(const int* __restrict__ deg_s, int* __restrict__ rp_s, int* __restrict__ bs_s,
                 const int* __restrict__ deg_t, int* __restrict__ rp_t, int* __restrict__ bs_t,
                 int n) {
    const int* in = blockIdx.y ? deg_t : deg_s;
    int* out = blockIdx.y ? rp_t : rp_s;
    int* bsum = blockIdx.y ? bs_t : bs_s;
    __shared__ int sh[1024];
    int t = threadIdx.x;
    int g = blockIdx.x * 1024 + t;
    int v = (g < n) ? in[g] : 0;
    sh[t] = v;
    __syncthreads();
    #pragma unroll
    for (int off = 1; off < 1024; off <<= 1) {
        int x = (t >= off) ? sh[t - off] : 0;
        __syncthreads();
        sh[t] += x;
        __syncthreads();
    }
    if (g < n) out[g] = sh[t] - v;
    if (t == 1023) bsum[blockIdx.x] = sh[1023];
}

__global__ __launch_bounds__(256)
void finalize2(int* __restrict__ rp_s, const int* __restrict__ bs_s, int* __restrict__ fil_s,
               int* __restrict__ rp_t, const int* __restrict__ bs_t, int* __restrict__ fil_t,
               int n, int nchunks, int total) {
    int* rowptr = blockIdx.y ? rp_t : rp_s;
    const int* bs = blockIdx.y ? bs_t : bs_s;
    int* fill = blockIdx.y ? fil_t : fil_s;
    __shared__ int sh[128];
    int t = threadIdx.x;
    if (t < 128) sh[t] = (t < nchunks) ? bs[t] : 0;
    __syncthreads();
    #pragma unroll
    for (int off = 1; off < 128; off <<= 1) {
        int x = (t >= off && t < 128) ? sh[t - off] : 0;
        __syncthreads();
        if (t < 128) sh[t] += x;
        __syncthreads();
    }
    int chunk = (blockIdx.x * 256) >> 10;
    int pre = chunk ? sh[chunk - 1] : 0;
    int g = blockIdx.x * 256 + t;
    if (g < n) {
        int v = rowptr[g] + pre;
        rowptr[g] = v;
        fill[g] = v;
    }
    if (g == n) rowptr[n] = total;
}

__device__ __forceinline__ void stcs_u32(uint32_t* addr, uint32_t v) {
    asm volatile("st.global.cs.u32 [%0], %1;" :: "l"(addr), "r"(v) : "memory");
}

__global__ __launch_bounds__(256)
void scatter_kernel(const int* __restrict__ erow, const int* __restrict__ ecol,
                    const float* __restrict__ ew,
                    int* __restrict__ fill_s, int* __restrict__ fill_t,
                    uint32_t* __restrict__ csr_s, uint32_t* __restrict__ csr_t, int E) {
    int e = blockIdx.x * blockDim.x + threadIdx.x;
    if (e >= E) return;
    int r = erow[e];
    int c = ecol[e];
    uint32_t qw = (uint32_t)__float2int_rn(ew[e] * W_SCALE);
    int ps = atomicAdd(&fill_s[r], 1);
    stcs_u32(csr_s + ps, ((uint32_t)c << 15) | qw);
    int pt = atomicAdd(&fill_t[c], 1);
    stcs_u32(csr_t + pt, ((uint32_t)r << 15) | qw);
}

// ======================= SPMM (64-dim fp16 gather, fp32 accumulate) =========
// HALF-WARP per node: 16 lanes x 8B = 128B row; 2 nodes per warp.
__global__ __launch_bounds__(256)
void spmm2_kernel(const int* __restrict__ rp_s, const int* __restrict__ rp_t,
                  const uint32_t* __restrict__ csr_s, const uint32_t* __restrict__ csr_t,
                  __half* __restrict__ hb, int h, int n) {
    int dir = blockIdx.y;
    const int* rowptr = dir ? rp_t : rp_s;
    const uint32_t* csr = dir ? csr_t : csr_s;
    const __half* x = hb + (size_t)(dir * 4 + h - 1) * CAPO;
    __half* next = hb + (size_t)(dir * 4 + h) * CAPO;

    int lane  = threadIdx.x & 31;
    int half  = lane >> 4;
    int hlane = lane & 15;
    int pairw = (int)((blockIdx.x * blockDim.x + threadIdx.x) >> 5);
    int node  = pairw * 2 + half;
    bool valid = (node < n);

    int beg = valid ? rowptr[node] : 0;
    int end = valid ? rowptr[node + 1] : 0;

    float acc[4] = {0.f, 0.f, 0.f, 0.f};
    const uint2* xb = (const uint2*)x + hlane;   // row stride = 16 uint2 (64 halves)

    int p = beg;
    while (true) {
        int cnt = end - p;
        if (cnt > 16) cnt = 16;
        unsigned any = __ballot_sync(0xffffffffu, cnt > 0);
        if (!any) break;
        uint32_t pk = 0;
        if (hlane < cnt) {
            asm volatile("ld.global.cs.u32 %0, [%1];" : "=r"(pk) : "l"(csr + p + hlane));
        }
        #pragma unroll
        for (int j = 0; j < 16; j++) {
            uint32_t pe = __shfl_sync(0xffffffffu, pk, (half << 4) + j);
            if (j < cnt) {
                int   c  = (int)(pe >> 15);
                float wv = (float)(pe & 0x7FFFu) * W_INV;
                uint2 raw = __ldg(xb + (size_t)c * 16);   // FIXED: 16 uint2 per row
                float2 v0 = __half22float2(*(__half2*)&raw.x);
                float2 v1 = __half22float2(*(__half2*)&raw.y);
                acc[0] = fmaf(wv, v0.x, acc[0]);
                acc[1] = fmaf(wv, v0.y, acc[1]);
                acc[2] = fmaf(wv, v1.x, acc[2]);
                acc[3] = fmaf(wv, v1.y, acc[3]);
            }
        }
        p += cnt;
    }

    if (valid) {
        __half2 o[2];
        o[0] = __floats2half2_rn(acc[0], acc[1]);
        o[1] = __floats2half2_rn(acc[2], acc[3]);
        *((uint2*)(next + (size_t)node * NOUT) + hlane) = *(uint2*)o;
    }
}

// ======================= tensor-core helpers ========================
__device__ __forceinline__ uint32_t smem_u32(const void* p) {
    return (uint32_t)__cvta_generic_to_shared(p);
}
__device__ __forceinline__ void ldsm_x4(uint32_t* r, uint32_t addr) {
    asm volatile("ldmatrix.sync.aligned.m8n8.x4.shared.b16 {%0,%1,%2,%3}, [%4];"
                 : "=r"(r[0]), "=r"(r[1]), "=r"(r[2]), "=r"(r[3]) : "r"(addr));
}
__device__ __forceinline__ void ldsm_x4_t(uint32_t* r, uint32_t addr) {
    asm volatile("ldmatrix.sync.aligned.m8n8.x4.trans.shared.b16 {%0,%1,%2,%3}, [%4];"
                 : "=r"(r[0]), "=r"(r[1]), "=r"(r[2]), "=r"(r[3]) : "r"(addr));
}
__device__ __forceinline__ void mma16816(float* c, const uint32_t* a,
                                         uint32_t b0, uint32_t b1) {
    asm volatile("mma.sync.aligned.m16n8k16.row.col.f32.f16.f16.f32 "
                 "{%0,%1,%2,%3}, {%4,%5,%6,%7}, {%8,%9}, {%0,%1,%2,%3};"
                 : "+f"(c[0]), "+f"(c[1]), "+f"(c[2]), "+f"(c[3])
                 : "r"(a[0]), "r"(a[1]), "r"(a[2]), "r"(a[3]), "r"(b0), "r"(b1));
}

#define A_STRIDE 40   // halves per row (32 + 8 pad)
#define W2_STRIDE 72  // halves per row (64 + 8 pad)

// ======================= input GEMM: y0 = A @ Wc + bc (fp16 out, 64 cols) ===
__global__ __launch_bounds__(256)
void gemm_input2_mma(const float* __restrict__ A0, const float* __restrict__ A1,
                     const float* __restrict__ wc, const float* __restrict__ bc,
                     __half* __restrict__ hb, int M) {
    const float* A  = blockIdx.y ? A1 : A0;
    const float* Wc = wc + (size_t)blockIdx.y * FEAT * NOUT;
    const float* Bc = bc + blockIdx.y * NOUT;
    __half* y = hb + (size_t)(blockIdx.y * 4) * CAPO;

    __shared__ __half Ah[128 * A_STRIDE];
    __shared__ __half Wh[32 * W2_STRIDE];
    int tid = threadIdx.x;
    int lane = tid & 31;
    int warp = tid >> 5;
    int wm = warp >> 1;
    int wn = warp & 1;
    int row0 = blockIdx.x * 128;

    float acc[2][4][4];
    #pragma unroll
    for (int i = 0; i < 2; i++)
        #pragma unroll
        for (int j = 0; j < 4; j++)
            #pragma unroll
            for (int k = 0; k < 4; k++) acc[i][j][k] = 0.f;

    for (int k0 = 0; k0 < FEAT; k0 += 32) {
        #pragma unroll
        for (int i = 0; i < 4; i++) {
            int f = tid + i * 256;
            int r = f >> 3;
            int cg = (f & 7) * 4;
            float4 v = make_float4(0.f, 0.f, 0.f, 0.f);
            if (row0 + r < M)
                v = *(const float4*)(A + (size_t)(row0 + r) * FEAT + k0 + cg);
            __half2 h0 = __floats2half2_rn(v.x, v.y);
            __half2 h1 = __floats2half2_rn(v.z, v.w);
            *(uint2*)&Ah[r * A_STRIDE + cg] = make_uint2(*(uint32_t*)&h0, *(uint32_t*)&h1);
        }
        #pragma unroll
        for (int i = 0; i < 2; i++) {
            int f = tid + i * 256;
            int r = f >> 4;
            int cg = (f & 15) * 4;
            float4 v = *(const float4*)(Wc + (size_t)(k0 + r) * NOUT + cg);
            __half2 h0 = __floats2half2_rn(v.x, v.y);
            __half2 h1 = __floats2half2_rn(v.z, v.w);
            *(uint2*)&Wh[r * W2_STRIDE + cg] = make_uint2(*(uint32_t*)&h0, *(uint32_t*)&h1);
        }
        __syncthreads();

        #pragma unroll
        for (int ks = 0; ks < 32; ks += 16) {
            uint32_t aF[2][4];
            #pragma unroll
            for (int mt = 0; mt < 2; mt++) {
                int r = wm * 32 + mt * 16 + (lane & 15);
                int c = ks + ((lane >> 4) << 3);
                ldsm_x4(aF[mt], smem_u32(&Ah[r * A_STRIDE + c]));
            }
            uint32_t bF[2][4];
            #pragma unroll
            for (int ng = 0; ng < 2; ng++) {
                int r = ks + ((lane >> 4) << 3) + (lane & 7);
                int c = wn * 32 + ng * 16 + (((lane >> 3) & 1) << 3);
                ldsm_x4_t(bF[ng], smem_u32(&Wh[r * W2_STRIDE + c]));
            }
            #pragma unroll
            for (int mt = 0; mt < 2; mt++)
                #pragma unroll
                for (int nt = 0; nt < 4; nt++) {
                    int ng = nt >> 1, sel = nt & 1;
                    mma16816(acc[mt][nt], aF[mt], bF[ng][sel], bF[ng][sel + 2]);
                }
        }
        __syncthreads();
    }

    #pragma unroll
    for (int mt = 0; mt < 2; mt++) {
        int r_ = row0 + wm * 32 + mt * 16 + (lane >> 2);
        #pragma unroll
        for (int nt = 0; nt < 4; nt++) {
            int c_ = wn * 32 + nt * 8 + (lane & 3) * 2;
            float b0 = __ldg(Bc + c_);
            float b1 = __ldg(Bc + c_ + 1);
            if (r_ < M) {
                __half2 hv = __floats2half2_rn(acc[mt][nt][0] + b0, acc[mt][nt][1] + b1);
                *(__half2*)(y + (size_t)r_ * NOUT + c_) = hv;
            }
            if (r_ + 8 < M) {
                __half2 hv = __floats2half2_rn(acc[mt][nt][2] + b0, acc[mt][nt][3] + b1);
                *(__half2*)(y + (size_t)(r_ + 8) * NOUT + c_) = hv;
            }
        }
    }
}

// ======================= final combine: out = b + Σ w_h * y_h ===============
__global__ __launch_bounds__(256)
void combine_kernel(const __half* __restrict__ hb,
                    const float* __restrict__ w_s, const float* __restrict__ w_t,
                    const float* __restrict__ bn, float* __restrict__ out, int M) {
    int i = blockIdx.x * blockDim.x + threadIdx.x;   // per 4 outputs
    int total = M * (NOUT / 4);
    if (i >= total) return;
    int col = (i * 4) & (NOUT - 1);
    float4 b = *(const float4*)(bn + col);
    float a0 = b.x, a1 = b.y, a2 = b.z, a3 = b.w;

    float wv[8];
    #pragma unroll
    for (int h = 0; h < 4; h++) {
        wv[h]     = __ldg(w_s + h);
        wv[4 + h] = __ldg(w_t + h);
    }
    #pragma unroll
    for (int k = 0; k < 8; k++) {
        uint2 raw = *((const uint2*)(hb + (size_t)k * CAPO) + i);
        float2 v0 = __half22float2(*(__half2*)&raw.x);
        float2 v1 = __half22float2(*(__half2*)&raw.y);
        float w = wv[k];
        a0 = fmaf(w, v0.x, a0);
        a1 = fmaf(w, v0.y, a1);
        a2 = fmaf(w, v1.x, a2);
        a3 = fmaf(w, v1.y, a3);
    }
    ((float4*)out)[i] = make_float4(a0, a1, a2, a3);
}

// ===========================================================================
extern "C" void kernel_launch(void* const* d_in, const int* in_sizes, int n_in,
                              void* d_out, int out_size) {
    const float* fsrc  = (const float*)d_in[0];
    const float* ftgt  = (const float*)d_in[1];
    const int*   erow  = (const int*)d_in[2];
    const int*   ecol  = (const int*)d_in[3];
    const float* ew    = (const float*)d_in[4];
    const float* W_src = (const float*)d_in[5];
    const float* b_src = (const float*)d_in[6];
    const float* W_tgt = (const float*)d_in[7];
    const float* b_tgt = (const float*)d_in[8];
    const float* w_s   = (const float*)d_in[9];
    const float* w_t   = (const float*)d_in[10];
    const float* W_nd  = (const float*)d_in[11];
    const float* b_nd  = (const float*)d_in[12];
    float* out = (float*)d_out;

    int M = in_sizes[0] / FEAT;
    int E = in_sizes[2];

    __half*   hb;     cudaGetSymbolAddress((void**)&hb, g_hbuf);
    int*      deg;    cudaGetSymbolAddress((void**)&deg, g_deg);
    int*      rowptr; cudaGetSymbolAddress((void**)&rowptr, g_rowptr);
    int*      fill;   cudaGetSymbolAddress((void**)&fill, g_fill);
    int*      bsum;   cudaGetSymbolAddress((void**)&bsum, g_bsum);
    uint32_t* csr;    cudaGetSymbolAddress((void**)&csr, g_csr);
    float*    wc;     cudaGetSymbolAddress((void**)&wc, g_wc);
    float*    bc;     cudaGetSymbolAddress((void**)&bc, g_bc);

    int* deg_s = deg;            int* deg_t = deg + NN;
    int* rp_s  = rowptr;         int* rp_t  = rowptr + (NN + 1);
    int* fil_s = fill;           int* fil_t = fill + NN;
    int* bs_s  = bsum;           int* bs_t  = bsum + 128;
    uint32_t* csr_s = csr;       uint32_t* csr_t = csr + NEDGE;

    int eblocks = (E + 255) / 256;
    int nchunks = (M + 1023) / 1024;

    bool fork = (g_side != 0 && g_evFork != 0 && g_evJoin != 0);
    cudaStream_t cs = fork ? g_side : 0;

    if (fork) {
        cudaEventRecord(g_evFork, 0);
        cudaStreamWaitEvent(g_side, g_evFork, 0);
    }

    // ---- CSR build (side stream) ----
    cudaMemsetAsync(deg_s, 0, 2 * NN * sizeof(int), cs);
    hist_kernel<<<eblocks, 256, 0, cs>>>(erow, ecol, deg_s, deg_t, E);
    {
        dim3 g(nchunks, 2);
        scan_chunk2<<<g, 1024, 0, cs>>>(deg_s, rp_s, bs_s, deg_t, rp_t, bs_t, M);
    }
    {
        dim3 g((M + 256) / 256, 2);
        finalize2<<<g, 256, 0, cs>>>(rp_s, bs_s, fil_s, rp_t, bs_t, fil_t, M, nchunks, E);
    }
    scatter_kernel<<<eblocks, 256, 0, cs>>>(erow, ecol, ew, fil_s, fil_t, csr_s, csr_t, E);

    // ---- weight fold + input projections (main stream, overlap CSR) ----
    {
        dim3 g(FEAT + 1, 2);
        fold_kernel<<<g, 64>>>(W_src, b_src, W_tgt, b_tgt, W_nd, wc, bc);
    }
    {
        dim3 g((M + 127) / 128, 2);
        gemm_input2_mma<<<g, 256>>>(fsrc, ftgt, wc, bc, hb, M);
    }

    if (fork) {
        cudaEventRecord(g_evJoin, g_side);
        cudaStreamWaitEvent(0, g_evJoin, 0);
    }

    // ---- hops (64-dim; both directions per launch; 2 nodes per warp) ----
    {
        int warps = (M + 1) / 2;
        dim3 g((warps * 32 + 255) / 256, 2);
        for (int h = 1; h <= HOPS; h++)
            spmm2_kernel<<<g, 256>>>(rp_s, rp_t, csr_s, csr_t, hb, h, M);
    }

    // ---- final combine (elementwise, replaces output GEMM) ----
    {
        int total = M * (NOUT / 4);
        combine_kernel<<<(total + 255) / 256, 256>>>(hb, w_s, w_t, b_nd, out, M);
    }
}